// round 14
// baseline (speedup 1.0000x reference)
#include <cuda_runtime.h>
#include <cuda_bf16.h>
#include <cuda_fp16.h>
#include <cstdint>
#include <cstddef>

// Problem constants
#define RB 64      // batch
#define RT 512     // time steps
#define RI 512     // input dim
#define RH 1024    // hidden dim
#define RO 512     // output dim
#define NBUF 4     // h ring-buffer depth

// ---------------------------------------------------------------------------
// Scratch (device globals; no allocation allowed)
// ---------------------------------------------------------------------------
__device__ __half g_xp[(size_t)RB * RT * RH];  // x_proj (fp16)
__device__ unsigned g_h2[NBUF * 512 * 64];     // h fp16 k-pairs: [buf][k2][b]
__device__ unsigned g_wflag[128 * 32];         // per-CTA counting write flags (4 quadrants)
__device__ unsigned g_rflag[128 * 32];         // per-CTA read flags, 128B apart

// ---------------------------------------------------------------------------
// Helpers
// ---------------------------------------------------------------------------
__device__ __forceinline__ void mma_f16(float* d,
                                        const unsigned* a, unsigned b0, unsigned b1) {
    asm("mma.sync.aligned.m16n8k16.row.col.f32.f16.f16.f32 "
        "{%0,%1,%2,%3},{%4,%5,%6,%7},{%8,%9},{%0,%1,%2,%3};"
        : "+f"(d[0]), "+f"(d[1]), "+f"(d[2]), "+f"(d[3])
        : "r"(a[0]), "r"(a[1]), "r"(a[2]), "r"(a[3]),
          "r"(b0), "r"(b1));
}
__device__ __forceinline__ void flag_release(unsigned* p, unsigned v) {
    asm volatile("st.release.gpu.global.u32 [%0],%1;" :: "l"(p), "r"(v) : "memory");
}
__device__ __forceinline__ unsigned flag_acquire(const unsigned* p) {
    unsigned v;
    asm volatile("ld.acquire.gpu.global.u32 %0,[%1];" : "=r"(v) : "l"(p) : "memory");
    return v;
}
__device__ __forceinline__ void flag_red_add(unsigned* p) {
    asm volatile("red.release.gpu.global.add.u32 [%0],1;" :: "l"(p) : "memory");
}
__device__ __forceinline__ unsigned ldcg_u32(const unsigned* p) {
    unsigned v;
    asm volatile("ld.global.cg.u32 %0,[%1];" : "=r"(v) : "l"(p));
    return v;
}
__device__ __forceinline__ unsigned h2pack(float a, float b) {
    __half2 h = __floats2half2_rn(a, b);   // low = a, high = b
    return *reinterpret_cast<unsigned*>(&h);
}
__device__ __forceinline__ unsigned short ld_u16_cs(const __half* p) {
    unsigned short v;
    asm volatile("ld.global.cs.u16 %0,[%1];" : "=h"(v) : "l"(p));
    return v;
}

// ---------------------------------------------------------------------------
// Init: zero flags, seed g_h2 buf0 from initial_hidden [b][j]
// ---------------------------------------------------------------------------
__global__ void rnn_init(const float* __restrict__ h0) {
    int bid = blockIdx.x;
    if (bid < 128) {
        int idx = bid * 256 + threadIdx.x;      // 0..32767 pairs
        int k2 = idx >> 6;                       // 0..511
        int b  = idx & 63;
        float v0 = h0[b * RH + 2 * k2];
        float v1 = h0[b * RH + 2 * k2 + 1];
        g_h2[k2 * 64 + b] = h2pack(v0, v1);
    } else {
        for (int i = threadIdx.x; i < 128 * 32; i += 256) {
            g_wflag[i] = 0;
            g_rflag[i] = 0;
        }
    }
}

// ---------------------------------------------------------------------------
// FP16 tensor-core GEMM, DOUBLE-BUFFERED smem (from R13, proven):
//   C[M,N](fp16) = A[M,K](fp32) @ B[K,N](fp32) + bias[N]
// ---------------------------------------------------------------------------
#define ASTR2 12
#define BSTR2 136
__global__ void __launch_bounds__(256) gemm_f16_bias_h16out(
    int M, int N, int K,
    const float* __restrict__ A, const float* __restrict__ B,
    const float* __restrict__ bias, __half* __restrict__ C)
{
    __shared__ unsigned As[2][128 * ASTR2];
    __shared__ unsigned Bs[2][8 * BSTR2];

    const int tid  = threadIdx.x;
    const int lane = tid & 31, wid = tid >> 5;
    const int g  = lane >> 2, tg = lane & 3;
    const int wm = (wid & 3) << 5;
    const int wn = (wid >> 2) << 6;
    const int bx = blockIdx.x << 7, by = blockIdx.y << 7;

    const int ar = tid >> 1, ah = (tid & 1) << 3;
    const float* Ag = A + (size_t)(by + ar) * K + ah;
    const int bk2 = tid >> 5, bn = (tid & 31) << 2;
    const float* Bg = B + (size_t)(2 * bk2) * N + bx + bn;

    const int nIters = K >> 4;

    float4 pa0, pa1, pb0, pb1;

    pa0 = *(const float4*)(Ag);
    pa1 = *(const float4*)(Ag + 4);
    pb0 = *(const float4*)(Bg);
    pb1 = *(const float4*)(Bg + (size_t)N);
    {
        uint4 va = make_uint4(h2pack(pa0.x, pa0.y), h2pack(pa0.z, pa0.w),
                              h2pack(pa1.x, pa1.y), h2pack(pa1.z, pa1.w));
        *(uint4*)&As[0][ar * ASTR2 + (ah >> 1)] = va;
        uint4 vb = make_uint4(h2pack(pb0.x, pb1.x), h2pack(pb0.y, pb1.y),
                              h2pack(pb0.z, pb1.z), h2pack(pb0.w, pb1.w));
        *(uint4*)&Bs[0][bk2 * BSTR2 + bn] = vb;
    }
    __syncthreads();
    if (nIters > 1) {
        pa0 = *(const float4*)(Ag + 16);
        pa1 = *(const float4*)(Ag + 20);
        pb0 = *(const float4*)(Bg + (size_t)16 * N);
        pb1 = *(const float4*)(Bg + (size_t)17 * N);
    }

    float acc[2][8][4];
#pragma unroll
    for (int i = 0; i < 2; i++)
#pragma unroll
        for (int j = 0; j < 8; j++)
#pragma unroll
            for (int l = 0; l < 4; l++) acc[i][j][l] = 0.f;

    for (int it = 0; it < nIters; ++it) {
        const int cur = it & 1;
        if (it + 1 < nIters) {
            const int nxt = cur ^ 1;
            uint4 va = make_uint4(h2pack(pa0.x, pa0.y), h2pack(pa0.z, pa0.w),
                                  h2pack(pa1.x, pa1.y), h2pack(pa1.z, pa1.w));
            *(uint4*)&As[nxt][ar * ASTR2 + (ah >> 1)] = va;
            uint4 vb = make_uint4(h2pack(pb0.x, pb1.x), h2pack(pb0.y, pb1.y),
                                  h2pack(pb0.z, pb1.z), h2pack(pb0.w, pb1.w));
            *(uint4*)&Bs[nxt][bk2 * BSTR2 + bn] = vb;
        }

        {
            unsigned af[2][4], bf[8][2];
#pragma unroll
            for (int mt = 0; mt < 2; mt++) {
                int row = wm + (mt << 4) + g;
                af[mt][0] = As[cur][row * ASTR2 + tg];
                af[mt][1] = As[cur][(row + 8) * ASTR2 + tg];
                af[mt][2] = As[cur][row * ASTR2 + tg + 4];
                af[mt][3] = As[cur][(row + 8) * ASTR2 + tg + 4];
            }
#pragma unroll
            for (int nt = 0; nt < 8; nt++) {
                int c = wn + (nt << 3) + g;
                bf[nt][0] = Bs[cur][tg * BSTR2 + c];
                bf[nt][1] = Bs[cur][(tg + 4) * BSTR2 + c];
            }
#pragma unroll
            for (int mt = 0; mt < 2; mt++)
#pragma unroll
                for (int nt = 0; nt < 8; nt++)
                    mma_f16(acc[mt][nt], af[mt], bf[nt][0], bf[nt][1]);
        }
        __syncthreads();

        if (it + 2 < nIters) {
            int k0 = (it + 2) << 4;
            pa0 = *(const float4*)(Ag + k0);
            pa1 = *(const float4*)(Ag + k0 + 4);
            pb0 = *(const float4*)(Bg + (size_t)k0 * N);
            pb1 = *(const float4*)(Bg + (size_t)(k0 + 1) * N);
        }
    }

#pragma unroll
    for (int mt = 0; mt < 2; mt++) {
        int r0 = by + wm + (mt << 4) + g;
#pragma unroll
        for (int nt = 0; nt < 8; nt++) {
            int col = bx + wn + (nt << 3) + (tg << 1);
            float b0v = bias[col], b1v = bias[col + 1];
            *(unsigned*)&C[(size_t)r0 * N + col] =
                h2pack(acc[mt][nt][0] + b0v, acc[mt][nt][1] + b1v);
            *(unsigned*)&C[(size_t)(r0 + 8) * N + col] =
                h2pack(acc[mt][nt][2] + b0v, acc[mt][nt][3] + b1v);
        }
    }
}

// ---------------------------------------------------------------------------
// Persistent recurrent scan v11 = R11/R13 proven core + FUSED output GEMM.
// Per step t (critical path identical to R13):
//   poll -> LDG ah(h(t)) -> 16 h-MMAs -> Red-h -> bp -> barrierA -> rflag
//   -> h-finalize (reduce, tanh, store h(t+1), wflag release)       [DONE]
//   then IN SLACK: 8 out-MMAs (ah x W_hy) -> Red-out -> barrierB
//   -> out-finalize: out[b, t-1, o] (256 threads).   Epilogue does t=RT-1.
// SMEM (u32): W2 16384 | Why 8192 | RedH 2x8704f | RedO 2x4352f  (~198KB)
// ---------------------------------------------------------------------------
#define SCAN_THREADS 512
#define SMEM_U32 (16384 + 8192 + 2*8704 + 2*4352)

__global__ void __launch_bounds__(SCAN_THREADS) rnn_scan_kernel(
    const float* __restrict__ W_hh, const float* __restrict__ W_hy,
    const float* __restrict__ b_y, float* __restrict__ out)
{
    extern __shared__ unsigned smu[];
    unsigned* W2   = smu;                       // [512 k2][32 j] fp16x2 swizzled
    unsigned* Why  = smu + 16384;               // [512 k2][16 o] fp16x2 swizzled
    float*    RedH0 = (float*)(smu + 24576);    // 16*544
    float*    RedH1 = RedH0 + 16 * 544;
    float*    RedO0 = (float*)(smu + 24576 + 2 * 8704);  // 16*272
    float*    RedO1 = RedO0 + 16 * 272;

    const int cta = blockIdx.x;
    const int g   = cta >> 5;
    const int cg  = cta & 31;
    const int gb0 = g << 4;
    const int gj0 = cg << 5;
    const int tid = threadIdx.x;
    const int lane = tid & 31;
    const int s    = tid >> 5;
    const int tg   = lane & 3;
    const int r    = lane >> 2;
    const int k2base = s << 5;

    // one-time: W_hh[:, gj0:gj0+32] -> fp16 k-pairs, swizzled
    for (int i = 0; i < 32; ++i) {
        int idx = i * SCAN_THREADS + tid;
        int k2 = idx >> 5, j = idx & 31;
        float w0 = W_hh[(size_t)(2 * k2) * RH + gj0 + j];
        float w1 = W_hh[(size_t)(2 * k2 + 1) * RH + gj0 + j];
        int dst = k2 * 32 + (j ^ ((k2 & 3) << 3));
        W2[dst] = h2pack(w0, w1);
    }
    // one-time: W_hy[:, 16cg:16cg+16] -> fp16 k-pairs, swizzled on k2&1
    for (int i = 0; i < 16; ++i) {
        int idx = i * SCAN_THREADS + tid;       // 0..8191
        int k2 = idx >> 4, c = idx & 15;
        float w0 = W_hy[(size_t)(2 * k2) * RO + (cg << 4) + c];
        float w1 = W_hy[(size_t)(2 * k2 + 1) * RO + (cg << 4) + c];
        int dst = k2 * 16 + (c ^ ((k2 & 1) << 3));
        Why[dst] = h2pack(w0, w1);
    }

    const int fb = tid >> 5;
    const int fj = tid & 31;
    // out bias (per finalize-out thread)
    float byv = 0.f;
    if (tid < 256) byv = b_y[(cg << 4) + (tid & 15)];

    const unsigned* prodflag =
        &g_wflag[((g << 5) + (s << 1) + (lane & 1)) * 32 + (((lane >> 1) & 3) << 3)];
    const unsigned* grflag = &g_rflag[((g << 5) + lane) * 32];
    unsigned* my_wflag_q = &g_wflag[cta * 32 + ((s & 3) << 3)];
    unsigned* my_rflag   = &g_rflag[cta * 32];

    __syncthreads();

    for (int t = 0; t < RT; ++t) {
        const unsigned bsrc = (unsigned)(t & 3) * (512 * 64);
        const unsigned bdst = (unsigned)((t + 1) & 3) * (512 * 64);
        float* RedT  = (t & 1) ? RedH1 : RedH0;
        float* RedOT = (t & 1) ? RedO1 : RedO0;

        const size_t xpi = ((size_t)(gb0 + fb) * RT + t) * RH + gj0 + fj;
        const float xpv = __half2float(__ushort_as_half(ld_u16_cs(&g_xp[xpi])));

        // 1) wait for this warp's 2 producers
        if (t > 0) {
            const unsigned tgt = 4u * (unsigned)t;
            if (lane < 8) {
                while (flag_acquire(prodflag) < tgt) { }
            }
            __syncwarp();
        }
        unsigned rv = 0;
        if (s == 15) rv = flag_acquire(grflag);

        // 2) direct LDG of A-fragments (h(t) = hidden(t-1))
        unsigned ah[4][4];
#pragma unroll
        for (int cc = 0; cc < 4; ++cc) {
            const int k2a = k2base + (cc << 3) + tg;
            ah[cc][0] = ldcg_u32(&g_h2[bsrc + k2a * 64 + gb0 + r]);
            ah[cc][1] = ldcg_u32(&g_h2[bsrc + k2a * 64 + gb0 + r + 8]);
            ah[cc][2] = ldcg_u32(&g_h2[bsrc + (k2a + 4) * 64 + gb0 + r]);
            ah[cc][3] = ldcg_u32(&g_h2[bsrc + (k2a + 4) * 64 + gb0 + r + 8]);
        }

        // 3) 16 h-MMAs, fp32 accum
        float acc[4][4];
#pragma unroll
        for (int nt = 0; nt < 4; nt++)
#pragma unroll
            for (int l = 0; l < 4; l++) acc[nt][l] = 0.f;

#pragma unroll
        for (int cc = 0; cc < 4; ++cc) {
            const int k2a = k2base + (cc << 3) + tg;
#pragma unroll
            for (int nt = 0; nt < 4; ++nt) {
                const int c0 = ((nt << 3) + r) ^ (tg << 3);
                mma_f16(acc[nt], ah[cc], W2[k2a * 32 + c0], W2[(k2a + 4) * 32 + c0]);
            }
        }

        // 4) Red-h partials
        {
            float* rp = RedT + s * 544;
#pragma unroll
            for (int nt = 0; nt < 4; ++nt) {
                int j0 = (nt << 3) + (tg << 1);
                rp[j0 * 17 + r]            = acc[nt][0];
                rp[(j0 + 1) * 17 + r]      = acc[nt][1];
                rp[j0 * 17 + r + 8]        = acc[nt][2];
                rp[(j0 + 1) * 17 + r + 8]  = acc[nt][3];
            }
        }
        // 5) warp 15: back-pressure
        if (s == 15) {
            int tgt = t - 2;
            if (tgt > 0) {
                while (!__all_sync(0xffffffffu, (int)rv >= tgt)) {
                    rv = flag_acquire(grflag);
                }
            }
        }
        __syncthreads();   // barrier A

        if (tid == 0) flag_release(my_rflag, (unsigned)(t + 1));

        // 7) h-finalize: reduce, tanh, store h(t+1), release  [CRITICAL END]
        {
            float v = 0.f;
            const float* rp = RedT + fj * 17 + fb;
#pragma unroll
            for (int ss = 0; ss < 16; ++ss) v += rp[ss * 544];
            float hv = tanhf(v + xpv);

            unsigned short hb = __half_as_ushort(__float2half_rn(hv));
            unsigned nb = __shfl_down_sync(0xffffffffu, (unsigned)hb, 1);
            if ((fj & 1) == 0) {
                int k2g = (cg << 4) + (fj >> 1);
                g_h2[bdst + k2g * 64 + gb0 + fb] =
                    (unsigned)hb | ((nb & 0xffffu) << 16);
            }
            __syncwarp();
            if (lane == 0) flag_red_add(my_wflag_q);

            if (t == RT - 1)
                out[(size_t)RB * RT * RO + (size_t)(gb0 + fb) * RH + gj0 + fj] = hv;
        }

        // 8) SHADOW: out-GEMM for time t-1 using live ah fragments
        if (t > 0) {
            float acco[2][4];
#pragma unroll
            for (int nt = 0; nt < 2; nt++)
#pragma unroll
                for (int l = 0; l < 4; l++) acco[nt][l] = 0.f;
#pragma unroll
            for (int cc = 0; cc < 4; ++cc) {
                const int k2a = k2base + (cc << 3) + tg;
#pragma unroll
                for (int nt = 0; nt < 2; ++nt) {
                    const int cW = ((nt << 3) + r) ^ ((k2a & 1) << 3);
                    mma_f16(acco[nt], ah[cc],
                            Why[k2a * 16 + cW], Why[(k2a + 4) * 16 + cW]);
                }
            }
            float* rpo = RedOT + s * 272;
#pragma unroll
            for (int nt = 0; nt < 2; ++nt) {
                int o0 = (nt << 3) + (tg << 1);
                rpo[o0 * 17 + r]            = acco[nt][0];
                rpo[(o0 + 1) * 17 + r]      = acco[nt][1];
                rpo[o0 * 17 + r + 8]        = acco[nt][2];
                rpo[(o0 + 1) * 17 + r + 8]  = acco[nt][3];
            }
        }
        __syncthreads();   // barrier B

        if (t > 0 && tid < 256) {
            int o = tid & 15, b = tid >> 4;
            float v = 0.f;
            const float* rp = RedOT + o * 17 + b;
#pragma unroll
            for (int ss = 0; ss < 16; ++ss) v += rp[ss * 272];
            out[((size_t)(gb0 + b) * RT + (t - 1)) * RO + (cg << 4) + o] = v + byv;
        }
    }

    // Epilogue: out for time RT-1 using h(RT) = hidden(RT-1)
    {
        const unsigned tgt = 4u * (unsigned)RT;
        if (lane < 8) {
            while (flag_acquire(prodflag) < tgt) { }
        }
        __syncwarp();
        const unsigned bsrc = (unsigned)(RT & 3) * (512 * 64);   // = 0

        unsigned ah[4][4];
#pragma unroll
        for (int cc = 0; cc < 4; ++cc) {
            const int k2a = k2base + (cc << 3) + tg;
            ah[cc][0] = ldcg_u32(&g_h2[bsrc + k2a * 64 + gb0 + r]);
            ah[cc][1] = ldcg_u32(&g_h2[bsrc + k2a * 64 + gb0 + r + 8]);
            ah[cc][2] = ldcg_u32(&g_h2[bsrc + (k2a + 4) * 64 + gb0 + r]);
            ah[cc][3] = ldcg_u32(&g_h2[bsrc + (k2a + 4) * 64 + gb0 + r + 8]);
        }
        float acco[2][4];
#pragma unroll
        for (int nt = 0; nt < 2; nt++)
#pragma unroll
            for (int l = 0; l < 4; l++) acco[nt][l] = 0.f;
#pragma unroll
        for (int cc = 0; cc < 4; ++cc) {
            const int k2a = k2base + (cc << 3) + tg;
#pragma unroll
            for (int nt = 0; nt < 2; ++nt) {
                const int cW = ((nt << 3) + r) ^ ((k2a & 1) << 3);
                mma_f16(acco[nt], ah[cc],
                        Why[k2a * 16 + cW], Why[(k2a + 4) * 16 + cW]);
            }
        }
        float* rpo = RedO0;
        {
            float* rpw = rpo + s * 272;
#pragma unroll
            for (int nt = 0; nt < 2; ++nt) {
                int o0 = (nt << 3) + (tg << 1);
                rpw[o0 * 17 + r]            = acco[nt][0];
                rpw[(o0 + 1) * 17 + r]      = acco[nt][1];
                rpw[o0 * 17 + r + 8]        = acco[nt][2];
                rpw[(o0 + 1) * 17 + r + 8]  = acco[nt][3];
            }
        }
        __syncthreads();
        if (tid < 256) {
            int o = tid & 15, b = tid >> 4;
            float v = 0.f;
            const float* rp = rpo + o * 17 + b;
#pragma unroll
            for (int ss = 0; ss < 16; ++ss) v += rp[ss * 272];
            out[((size_t)(gb0 + b) * RT + (RT - 1)) * RO + (cg << 4) + o] = v + byv;
        }
    }
}

// ---------------------------------------------------------------------------
// Launch
// ---------------------------------------------------------------------------
extern "C" void kernel_launch(void* const* d_in, const int* in_sizes, int n_in,
                              void* d_out, int out_size)
{
    const float* inputs = (const float*)d_in[0];
    const float* h0     = (const float*)d_in[1];
    const float* W_xh   = (const float*)d_in[2];
    const float* W_hh   = (const float*)d_in[3];
    const float* W_hy   = (const float*)d_in[4];
    const float* b_h    = (const float*)d_in[5];
    const float* b_y    = (const float*)d_in[6];
    float* out = (float*)d_out;

    void* xp_ptr = nullptr;
    cudaGetSymbolAddress(&xp_ptr, g_xp);
    __half* xp = (__half*)xp_ptr;

    cudaFuncSetAttribute(rnn_scan_kernel,
                         cudaFuncAttributeMaxDynamicSharedMemorySize,
                         SMEM_U32 * (int)sizeof(unsigned));

    // 0) reset flags, seed h0 as fp16 pairs
    rnn_init<<<129, 256>>>(h0);

    // 1) x_proj = inputs @ W_xh + b_h   (fp16 TC, double-buffered, fp16 out)
    gemm_f16_bias_h16out<<<dim3(RH / 128, (RB * RT) / 128), 256>>>(
        RB * RT, RH, RI, inputs, W_xh, b_h, xp);

    // 2) persistent recurrent scan with FUSED output GEMM (replaces GEMM3)
    rnn_scan_kernel<<<128, SCAN_THREADS, SMEM_U32 * sizeof(unsigned)>>>(
        W_hh, W_hy, b_y, out);
}

// round 15
// speedup vs baseline: 1.1188x; 1.1188x over previous
#include <cuda_runtime.h>
#include <cuda_bf16.h>
#include <cuda_fp16.h>
#include <cstdint>
#include <cstddef>

// Problem constants
#define RB 64      // batch
#define RT 512     // time steps
#define RI 512     // input dim
#define RH 1024    // hidden dim
#define RO 512     // output dim
#define NBUF 4     // h ring-buffer depth

// ---------------------------------------------------------------------------
// Scratch (device globals; no allocation allowed)
// ---------------------------------------------------------------------------
__device__ __half g_xp[(size_t)RB * RT * RH];  // x_proj (fp16), then hidden states (in place)
__device__ unsigned g_h2[NBUF * 512 * 64];     // h fp16 k-pairs: [buf][k2][b]
__device__ unsigned g_wflag[128 * 32];         // per-CTA counting write flags (4 quadrants)
__device__ unsigned g_rflag[128 * 32];         // per-CTA read flags, 128B apart

// ---------------------------------------------------------------------------
// Helpers
// ---------------------------------------------------------------------------
// fp16 MMA, fp32 accumulate
__device__ __forceinline__ void mma_f16(float* d,
                                        const unsigned* a, unsigned b0, unsigned b1) {
    asm("mma.sync.aligned.m16n8k16.row.col.f32.f16.f16.f32 "
        "{%0,%1,%2,%3},{%4,%5,%6,%7},{%8,%9},{%0,%1,%2,%3};"
        : "+f"(d[0]), "+f"(d[1]), "+f"(d[2]), "+f"(d[3])
        : "r"(a[0]), "r"(a[1]), "r"(a[2]), "r"(a[3]),
          "r"(b0), "r"(b1));
}
// fp16 MMA, fp16 accumulate (half issue cost; used in short k-windows)
__device__ __forceinline__ void mma_f16acc(unsigned* d,
                                           const unsigned* a, unsigned b0, unsigned b1) {
    asm("mma.sync.aligned.m16n8k16.row.col.f16.f16.f16.f16 "
        "{%0,%1},{%2,%3,%4,%5},{%6,%7},{%0,%1};"
        : "+r"(d[0]), "+r"(d[1])
        : "r"(a[0]), "r"(a[1]), "r"(a[2]), "r"(a[3]),
          "r"(b0), "r"(b1));
}
__device__ __forceinline__ void flag_release(unsigned* p, unsigned v) {
    asm volatile("st.release.gpu.global.u32 [%0],%1;" :: "l"(p), "r"(v) : "memory");
}
__device__ __forceinline__ unsigned flag_acquire(const unsigned* p) {
    unsigned v;
    asm volatile("ld.acquire.gpu.global.u32 %0,[%1];" : "=r"(v) : "l"(p) : "memory");
    return v;
}
__device__ __forceinline__ void flag_red_add(unsigned* p) {
    asm volatile("red.release.gpu.global.add.u32 [%0],1;" :: "l"(p) : "memory");
}
__device__ __forceinline__ unsigned ldcg_u32(const unsigned* p) {
    unsigned v;
    asm volatile("ld.global.cg.u32 %0,[%1];" : "=r"(v) : "l"(p));
    return v;
}
__device__ __forceinline__ unsigned h2pack(float a, float b) {
    __half2 h = __floats2half2_rn(a, b);   // low = a, high = b
    return *reinterpret_cast<unsigned*>(&h);
}
__device__ __forceinline__ void st_u16_cs(__half* p, unsigned short v) {
    asm volatile("st.global.cs.u16 [%0],%1;" :: "l"(p), "h"(v) : "memory");
}
__device__ __forceinline__ unsigned short ld_u16_cs(const __half* p) {
    unsigned short v;
    asm volatile("ld.global.cs.u16 %0,[%1];" : "=h"(v) : "l"(p));
    return v;
}

// ---------------------------------------------------------------------------
// Init: zero flags, seed g_h2 buf0 from initial_hidden [b][j]
// ---------------------------------------------------------------------------
__global__ void rnn_init(const float* __restrict__ h0) {
    int bid = blockIdx.x;
    if (bid < 128) {
        int idx = bid * 256 + threadIdx.x;      // 0..32767 pairs
        int k2 = idx >> 6;                       // 0..511
        int b  = idx & 63;
        float v0 = h0[b * RH + 2 * k2];
        float v1 = h0[b * RH + 2 * k2 + 1];
        g_h2[k2 * 64 + b] = h2pack(v0, v1);
    } else {
        for (int i = threadIdx.x; i < 128 * 32; i += 256) {
            g_wflag[i] = 0;
            g_rflag[i] = 0;
        }
    }
}

// ---------------------------------------------------------------------------
// FP16 tensor-core GEMM, DOUBLE-BUFFERED smem (R13, proven):
//   C[M,N](fp16) = A[M,K](fp32) @ B[K,N](fp32) + bias[N]
// ---------------------------------------------------------------------------
#define ASTR2 12
#define BSTR2 136
__global__ void __launch_bounds__(256) gemm_f16_bias_h16out(
    int M, int N, int K,
    const float* __restrict__ A, const float* __restrict__ B,
    const float* __restrict__ bias, __half* __restrict__ C)
{
    __shared__ unsigned As[2][128 * ASTR2];
    __shared__ unsigned Bs[2][8 * BSTR2];

    const int tid  = threadIdx.x;
    const int lane = tid & 31, wid = tid >> 5;
    const int g  = lane >> 2, tg = lane & 3;
    const int wm = (wid & 3) << 5;
    const int wn = (wid >> 2) << 6;
    const int bx = blockIdx.x << 7, by = blockIdx.y << 7;

    const int ar = tid >> 1, ah = (tid & 1) << 3;
    const float* Ag = A + (size_t)(by + ar) * K + ah;
    const int bk2 = tid >> 5, bn = (tid & 31) << 2;
    const float* Bg = B + (size_t)(2 * bk2) * N + bx + bn;

    const int nIters = K >> 4;

    float4 pa0, pa1, pb0, pb1;

    pa0 = *(const float4*)(Ag);
    pa1 = *(const float4*)(Ag + 4);
    pb0 = *(const float4*)(Bg);
    pb1 = *(const float4*)(Bg + (size_t)N);
    {
        uint4 va = make_uint4(h2pack(pa0.x, pa0.y), h2pack(pa0.z, pa0.w),
                              h2pack(pa1.x, pa1.y), h2pack(pa1.z, pa1.w));
        *(uint4*)&As[0][ar * ASTR2 + (ah >> 1)] = va;
        uint4 vb = make_uint4(h2pack(pb0.x, pb1.x), h2pack(pb0.y, pb1.y),
                              h2pack(pb0.z, pb1.z), h2pack(pb0.w, pb1.w));
        *(uint4*)&Bs[0][bk2 * BSTR2 + bn] = vb;
    }
    __syncthreads();
    if (nIters > 1) {
        pa0 = *(const float4*)(Ag + 16);
        pa1 = *(const float4*)(Ag + 20);
        pb0 = *(const float4*)(Bg + (size_t)16 * N);
        pb1 = *(const float4*)(Bg + (size_t)17 * N);
    }

    float acc[2][8][4];
#pragma unroll
    for (int i = 0; i < 2; i++)
#pragma unroll
        for (int j = 0; j < 8; j++)
#pragma unroll
            for (int l = 0; l < 4; l++) acc[i][j][l] = 0.f;

    for (int it = 0; it < nIters; ++it) {
        const int cur = it & 1;
        if (it + 1 < nIters) {
            const int nxt = cur ^ 1;
            uint4 va = make_uint4(h2pack(pa0.x, pa0.y), h2pack(pa0.z, pa0.w),
                                  h2pack(pa1.x, pa1.y), h2pack(pa1.z, pa1.w));
            *(uint4*)&As[nxt][ar * ASTR2 + (ah >> 1)] = va;
            uint4 vb = make_uint4(h2pack(pb0.x, pb1.x), h2pack(pb0.y, pb1.y),
                                  h2pack(pb0.z, pb1.z), h2pack(pb0.w, pb1.w));
            *(uint4*)&Bs[nxt][bk2 * BSTR2 + bn] = vb;
        }

        {
            unsigned af[2][4], bf[8][2];
#pragma unroll
            for (int mt = 0; mt < 2; mt++) {
                int row = wm + (mt << 4) + g;
                af[mt][0] = As[cur][row * ASTR2 + tg];
                af[mt][1] = As[cur][(row + 8) * ASTR2 + tg];
                af[mt][2] = As[cur][row * ASTR2 + tg + 4];
                af[mt][3] = As[cur][(row + 8) * ASTR2 + tg + 4];
            }
#pragma unroll
            for (int nt = 0; nt < 8; nt++) {
                int c = wn + (nt << 3) + g;
                bf[nt][0] = Bs[cur][tg * BSTR2 + c];
                bf[nt][1] = Bs[cur][(tg + 4) * BSTR2 + c];
            }
#pragma unroll
            for (int mt = 0; mt < 2; mt++)
#pragma unroll
                for (int nt = 0; nt < 8; nt++)
                    mma_f16(acc[mt][nt], af[mt], bf[nt][0], bf[nt][1]);
        }
        __syncthreads();

        if (it + 2 < nIters) {
            int k0 = (it + 2) << 4;
            pa0 = *(const float4*)(Ag + k0);
            pa1 = *(const float4*)(Ag + k0 + 4);
            pb0 = *(const float4*)(Bg + (size_t)k0 * N);
            pb1 = *(const float4*)(Bg + (size_t)(k0 + 1) * N);
        }
    }

#pragma unroll
    for (int mt = 0; mt < 2; mt++) {
        int r0 = by + wm + (mt << 4) + g;
#pragma unroll
        for (int nt = 0; nt < 8; nt++) {
            int col = bx + wn + (nt << 3) + (tg << 1);
            float b0v = bias[col], b1v = bias[col + 1];
            *(unsigned*)&C[(size_t)r0 * N + col] =
                h2pack(acc[mt][nt][0] + b0v, acc[mt][nt][1] + b1v);
            *(unsigned*)&C[(size_t)(r0 + 8) * N + col] =
                h2pack(acc[mt][nt][2] + b0v, acc[mt][nt][3] + b1v);
        }
    }
}

// ---------------------------------------------------------------------------
// FP16 tensor-core GEMM, fp16 A input, fp32 output, DOUBLE-BUFFERED (R13).
// ---------------------------------------------------------------------------
__global__ void __launch_bounds__(256) gemm_f16A_bias(
    int M, int N, int K,
    const __half* __restrict__ A, const float* __restrict__ B,
    const float* __restrict__ bias, float* __restrict__ C)
{
    __shared__ unsigned As[2][128 * ASTR2];
    __shared__ unsigned Bs[2][8 * BSTR2];

    const int tid  = threadIdx.x;
    const int lane = tid & 31, wid = tid >> 5;
    const int g  = lane >> 2, tg = lane & 3;
    const int wm = (wid & 3) << 5;
    const int wn = (wid >> 2) << 6;
    const int bx = blockIdx.x << 7, by = blockIdx.y << 7;

    const int ar = tid >> 1, ah = (tid & 1) << 3;
    const __half* Ag = A + (size_t)(by + ar) * K + ah;
    const int bk2 = tid >> 5, bn = (tid & 31) << 2;
    const float* Bg = B + (size_t)(2 * bk2) * N + bx + bn;

    const int nIters = K >> 4;

    uint4  pa;
    float4 pb0, pb1;

    pa  = *(const uint4*)(Ag);
    pb0 = *(const float4*)(Bg);
    pb1 = *(const float4*)(Bg + (size_t)N);
    {
        *(uint4*)&As[0][ar * ASTR2 + (ah >> 1)] = pa;
        uint4 vb = make_uint4(h2pack(pb0.x, pb1.x), h2pack(pb0.y, pb1.y),
                              h2pack(pb0.z, pb1.z), h2pack(pb0.w, pb1.w));
        *(uint4*)&Bs[0][bk2 * BSTR2 + bn] = vb;
    }
    __syncthreads();
    if (nIters > 1) {
        pa  = *(const uint4*)(Ag + 16);
        pb0 = *(const float4*)(Bg + (size_t)16 * N);
        pb1 = *(const float4*)(Bg + (size_t)17 * N);
    }

    float acc[2][8][4];
#pragma unroll
    for (int i = 0; i < 2; i++)
#pragma unroll
        for (int j = 0; j < 8; j++)
#pragma unroll
            for (int l = 0; l < 4; l++) acc[i][j][l] = 0.f;

    for (int it = 0; it < nIters; ++it) {
        const int cur = it & 1;
        if (it + 1 < nIters) {
            const int nxt = cur ^ 1;
            *(uint4*)&As[nxt][ar * ASTR2 + (ah >> 1)] = pa;
            uint4 vb = make_uint4(h2pack(pb0.x, pb1.x), h2pack(pb0.y, pb1.y),
                                  h2pack(pb0.z, pb1.z), h2pack(pb0.w, pb1.w));
            *(uint4*)&Bs[nxt][bk2 * BSTR2 + bn] = vb;
        }

        {
            unsigned af[2][4], bf[8][2];
#pragma unroll
            for (int mt = 0; mt < 2; mt++) {
                int row = wm + (mt << 4) + g;
                af[mt][0] = As[cur][row * ASTR2 + tg];
                af[mt][1] = As[cur][(row + 8) * ASTR2 + tg];
                af[mt][2] = As[cur][row * ASTR2 + tg + 4];
                af[mt][3] = As[cur][(row + 8) * ASTR2 + tg + 4];
            }
#pragma unroll
            for (int nt = 0; nt < 8; nt++) {
                int c = wn + (nt << 3) + g;
                bf[nt][0] = Bs[cur][tg * BSTR2 + c];
                bf[nt][1] = Bs[cur][(tg + 4) * BSTR2 + c];
            }
#pragma unroll
            for (int mt = 0; mt < 2; mt++)
#pragma unroll
                for (int nt = 0; nt < 8; nt++)
                    mma_f16(acc[mt][nt], af[mt], bf[nt][0], bf[nt][1]);
        }
        __syncthreads();

        if (it + 2 < nIters) {
            int k0 = (it + 2) << 4;
            pa  = *(const uint4*)(Ag + k0);
            pb0 = *(const float4*)(Bg + (size_t)k0 * N);
            pb1 = *(const float4*)(Bg + (size_t)(k0 + 1) * N);
        }
    }

#pragma unroll
    for (int mt = 0; mt < 2; mt++) {
        int r0 = by + wm + (mt << 4) + g;
#pragma unroll
        for (int nt = 0; nt < 8; nt++) {
            int col = bx + wn + (nt << 3) + (tg << 1);
            float b0v = bias[col], b1v = bias[col + 1];
            float2 v0 = make_float2(acc[mt][nt][0] + b0v, acc[mt][nt][1] + b1v);
            float2 v1 = make_float2(acc[mt][nt][2] + b0v, acc[mt][nt][3] + b1v);
            *(float2*)&C[(size_t)r0 * N + col]       = v0;
            *(float2*)&C[(size_t)(r0 + 8) * N + col] = v1;
        }
    }
}

// ---------------------------------------------------------------------------
// Persistent recurrent scan — R11/R13 proven protocol; h-MMAs now run with
// fp16 accumulators in k=32 windows (2 MMAs), promoted to fp32 per window.
// Halves the dominant MMA issue term (rt8 vs rt16 per SMSP).
// ---------------------------------------------------------------------------
#define SCAN_THREADS 512
#define SMEM_U32 (16384 + 2 * 16 * 544)

__global__ void __launch_bounds__(SCAN_THREADS) rnn_scan_kernel(
    const float* __restrict__ W_hh, float* __restrict__ out)
{
    extern __shared__ unsigned smu[];
    unsigned* W2   = smu;                     // [k2=512][32j] fp16x2, swizzled (64KB)
    float*    Red0 = (float*)(smu + 16384);
    float*    Red1 = Red0 + 16 * 544;

    const int cta = blockIdx.x;
    const int g   = cta >> 5;
    const int cg  = cta & 31;
    const int gb0 = g << 4;
    const int gj0 = cg << 5;
    const int tid = threadIdx.x;
    const int lane = tid & 31;
    const int s    = tid >> 5;
    const int tg   = lane & 3;
    const int r    = lane >> 2;
    const int k2base = s << 5;

    // one-time: W_hh[:, gj0:gj0+32] -> fp16 k-pairs, swizzled
    for (int i = 0; i < 32; ++i) {
        int idx = i * SCAN_THREADS + tid;
        int k2 = idx >> 5, j = idx & 31;
        float w0 = W_hh[(size_t)(2 * k2) * RH + gj0 + j];
        float w1 = W_hh[(size_t)(2 * k2 + 1) * RH + gj0 + j];
        int dst = k2 * 32 + (j ^ ((k2 & 3) << 3));
        W2[dst] = h2pack(w0, w1);
    }

    const int fb = tid >> 5;
    const int fj = tid & 31;

    const unsigned* prodflag =
        &g_wflag[((g << 5) + (s << 1) + (lane & 1)) * 32 + (((lane >> 1) & 3) << 3)];
    const unsigned* grflag = &g_rflag[((g << 5) + lane) * 32];
    unsigned* my_wflag_q = &g_wflag[cta * 32 + ((s & 3) << 3)];
    unsigned* my_rflag   = &g_rflag[cta * 32];

    __syncthreads();

    for (int t = 0; t < RT; ++t) {
        const unsigned bsrc = (unsigned)(t & 3) * (512 * 64);
        const unsigned bdst = (unsigned)((t + 1) & 3) * (512 * 64);
        float* RedT = (t & 1) ? Red1 : Red0;

        const size_t xpi = ((size_t)(gb0 + fb) * RT + t) * RH + gj0 + fj;
        const float xpv = __half2float(__ushort_as_half(ld_u16_cs(&g_xp[xpi])));

        // 1) wait for this warp's 2 producers (8 distinct flags, lanes 0-7)
        if (t > 0) {
            const unsigned tgt = 4u * (unsigned)t;
            if (lane < 8) {
                while (flag_acquire(prodflag) < tgt) { }
            }
            __syncwarp();
        }
        unsigned rv = 0;
        if (s == 15) rv = flag_acquire(grflag);

        // 2) direct LDG of A-fragments (16 x LDG.32)
        unsigned ah[4][4];
#pragma unroll
        for (int cc = 0; cc < 4; ++cc) {
            const int k2a = k2base + (cc << 3) + tg;
            ah[cc][0] = ldcg_u32(&g_h2[bsrc + k2a * 64 + gb0 + r]);
            ah[cc][1] = ldcg_u32(&g_h2[bsrc + k2a * 64 + gb0 + r + 8]);
            ah[cc][2] = ldcg_u32(&g_h2[bsrc + (k2a + 4) * 64 + gb0 + r]);
            ah[cc][3] = ldcg_u32(&g_h2[bsrc + (k2a + 4) * 64 + gb0 + r + 8]);
        }

        // 3) 16 MMAs in fp16-acc k=32 windows, promoted to fp32 per window
        float acc[4][4];
#pragma unroll
        for (int nt = 0; nt < 4; nt++)
#pragma unroll
            for (int l = 0; l < 4; l++) acc[nt][l] = 0.f;

#pragma unroll
        for (int pr = 0; pr < 2; ++pr) {
            unsigned hacc[4][2];
#pragma unroll
            for (int nt = 0; nt < 4; nt++) { hacc[nt][0] = 0u; hacc[nt][1] = 0u; }
#pragma unroll
            for (int ci = 0; ci < 2; ++ci) {
                const int cc = (pr << 1) + ci;
                const int k2a = k2base + (cc << 3) + tg;
#pragma unroll
                for (int nt = 0; nt < 4; ++nt) {
                    const int c0 = ((nt << 3) + r) ^ (tg << 3);
                    mma_f16acc(hacc[nt], ah[cc],
                               W2[k2a * 32 + c0], W2[(k2a + 4) * 32 + c0]);
                }
            }
#pragma unroll
            for (int nt = 0; nt < 4; ++nt) {
                float2 a01 = __half22float2(*reinterpret_cast<__half2*>(&hacc[nt][0]));
                float2 a23 = __half22float2(*reinterpret_cast<__half2*>(&hacc[nt][1]));
                acc[nt][0] += a01.x; acc[nt][1] += a01.y;
                acc[nt][2] += a23.x; acc[nt][3] += a23.y;
            }
        }

        // 4) write partials: RedT[s*544 + j*17 + b]
        {
            float* rp = RedT + s * 544;
#pragma unroll
            for (int nt = 0; nt < 4; ++nt) {
                int j0 = (nt << 3) + (tg << 1);
                rp[j0 * 17 + r]            = acc[nt][0];
                rp[(j0 + 1) * 17 + r]      = acc[nt][1];
                rp[j0 * 17 + r + 8]        = acc[nt][2];
                rp[(j0 + 1) * 17 + r + 8]  = acc[nt][3];
            }
        }
        // 5) warp 15: back-pressure
        if (s == 15) {
            int tgt = t - 2;
            if (tgt > 0) {
                while (!__all_sync(0xffffffffu, (int)rv >= tgt)) {
                    rv = flag_acquire(grflag);
                }
            }
        }
        __syncthreads();

        if (tid == 0) flag_release(my_rflag, (unsigned)(t + 1));

        // 7) finalize: reduce 16 partials, tanh, store h, release
        {
            float v = 0.f;
            const float* rp = RedT + fj * 17 + fb;
#pragma unroll
            for (int ss = 0; ss < 16; ++ss) v += rp[ss * 544];
            float hv = tanhf(v + xpv);

            unsigned short hb = __half_as_ushort(__float2half_rn(hv));
            unsigned nb = __shfl_down_sync(0xffffffffu, (unsigned)hb, 1);
            if ((fj & 1) == 0) {
                int k2g = (cg << 4) + (fj >> 1);
                g_h2[bdst + k2g * 64 + gb0 + fb] =
                    (unsigned)hb | ((nb & 0xffffu) << 16);
            }
            __syncwarp();
            if (lane == 0) flag_red_add(my_wflag_q);

            st_u16_cs(&g_xp[xpi], hb);   // fp16 hidden-state history (GEMM3 input)
            if (t == RT - 1)
                out[(size_t)RB * RT * RO + (size_t)(gb0 + fb) * RH + gj0 + fj] = hv;
        }
    }
}

// ---------------------------------------------------------------------------
// Launch
// ---------------------------------------------------------------------------
extern "C" void kernel_launch(void* const* d_in, const int* in_sizes, int n_in,
                              void* d_out, int out_size)
{
    const float* inputs = (const float*)d_in[0];
    const float* h0     = (const float*)d_in[1];
    const float* W_xh   = (const float*)d_in[2];
    const float* W_hh   = (const float*)d_in[3];
    const float* W_hy   = (const float*)d_in[4];
    const float* b_h    = (const float*)d_in[5];
    const float* b_y    = (const float*)d_in[6];
    float* out = (float*)d_out;

    void* xp_ptr = nullptr;
    cudaGetSymbolAddress(&xp_ptr, g_xp);
    __half* xp = (__half*)xp_ptr;

    cudaFuncSetAttribute(rnn_scan_kernel,
                         cudaFuncAttributeMaxDynamicSharedMemorySize,
                         SMEM_U32 * (int)sizeof(unsigned));

    // 0) reset flags, seed h0 as fp16 pairs
    rnn_init<<<129, 256>>>(h0);

    // 1) x_proj = inputs @ W_xh + b_h   (fp16 TC, double-buffered, fp16 out)
    gemm_f16_bias_h16out<<<dim3(RH / 128, (RB * RT) / 128), 256>>>(
        RB * RT, RH, RI, inputs, W_xh, b_h, xp);

    // 2) persistent recurrent scan (R13 protocol, fp16-acc windowed MMAs)
    rnn_scan_kernel<<<128, SCAN_THREADS, SMEM_U32 * sizeof(unsigned)>>>(W_hh, out);

    // 3) outputs = hidden_states(fp16) @ W_hy + b_y   (fp16 TC, double-buffered)
    gemm_f16A_bias<<<dim3(RO / 128, (RB * RT) / 128), 256>>>(
        RB * RT, RO, RH, xp, W_hy, b_y, out);
}